// round 15
// baseline (speedup 1.0000x reference)
#include <cuda_runtime.h>
#include <math.h>
#include <limits.h>

// WARP loss, R15: warp-per-row BIDIRECTIONAL scan + lazy-16 gather.
// Positive index is uniform -> scan from both ends simultaneously: round r
// tests front chunk r and back chunk r (2KB each). Rounds to hit =
// ceil(min(p, Y-p)/chunk): E=5.4, max 10 (vs 8.2/16 forward) at IDENTICAL
// expected traffic. Two directions = 2 independent loads per round; plus
// R13-style 1-ahead prefetch. 64-thr blocks (grid 2048, ~14/SM, balanced).

#define FULL 0xFFFFFFFFu
#define BATCH1 16
#define CV 4                        // uint4 per lane per chunk -> 2KB chunks
#define CHUNK (CV * 32)             // 128 vec(16B) per chunk

__device__ __forceinline__ void load_front(uint4 (&buf)[CV], const uint4* tv,
                                           int ch, int lane, int nvec) {
#pragma unroll
    for (int k = 0; k < CV; k++) {
        const int i = ch * CHUNK + k * 32 + lane;
        buf[k] = (i < nvec) ? __ldg(&tv[i]) : make_uint4(0u, 0u, 0u, 0u);
    }
}
__device__ __forceinline__ void load_back(uint4 (&buf)[CV], const uint4* tv,
                                          int ch, int lane, int nvec) {
#pragma unroll
    for (int k = 0; k < CV; k++) {
        const int i = nvec - (ch + 1) * CHUNK + k * 32 + lane;
        buf[k] = (i >= 0 && i < nvec) ? __ldg(&tv[i]) : make_uint4(0u, 0u, 0u, 0u);
    }
}

__device__ __forceinline__ unsigned orv(const uint4 (&buf)[CV]) {
    unsigned f = 0u;
#pragma unroll
    for (int k = 0; k < CV; k++) f |= (buf[k].x | buf[k].y | buf[k].z | buf[k].w);
    return f;
}
__device__ __forceinline__ void locate_front(const uint4 (&buf)[CV], int ch,
                                             int lane, int& p) {
#pragma unroll
    for (int k = 0; k < CV; k++) {
        const int i = ch * CHUNK + k * 32 + lane;
        if (buf[k].x) p = 4 * i;
        if (buf[k].y) p = 4 * i + 1;
        if (buf[k].z) p = 4 * i + 2;
        if (buf[k].w) p = 4 * i + 3;
    }
}
__device__ __forceinline__ void locate_back(const uint4 (&buf)[CV], int ch,
                                            int lane, int nvec, int& p) {
#pragma unroll
    for (int k = 0; k < CV; k++) {
        const int i = nvec - (ch + 1) * CHUNK + k * 32 + lane;
        if (buf[k].x) p = 4 * i;
        if (buf[k].y) p = 4 * i + 1;
        if (buf[k].z) p = 4 * i + 2;
        if (buf[k].w) p = 4 * i + 3;
    }
}

__global__ __launch_bounds__(64, 16)
void warp_loss_kernel(const float* __restrict__ input,
                      const float* __restrict__ target,
                      const int*   __restrict__ neg,
                      float* __restrict__ out,
                      int B, int T) {
    constexpr int Y    = 10000;
    constexpr int nvec = Y >> 2;                          // 2500 vec
    constexpr int NR   = (nvec + 2 * CHUNK - 1) / (2 * CHUNK);  // 10 rounds

    const int gw   = blockIdx.x * 2 + (threadIdx.x >> 5);
    const int lane = threadIdx.x & 31;
    if (gw >= B) return;                                  // warp-uniform

    const float* irow = input  + (size_t)gw * Y;
    const uint4* tv   = reinterpret_cast<const uint4*>(target + (size_t)gw * Y);

    // --- eager gather of first BATCH1 trials (independent of sp) ---
    int c_pre = 0;
    if (lane < BATCH1) c_pre = __ldg(&neg[(size_t)gw * T + lane]);
    const float sc_pre = __ldg(&irow[c_pre]);             // lanes>=16: bcast

    // --- bidirectional scan, 1-ahead prefetch ---
    int pos = -1;
    {
        uint4 fA[CV], bA[CV], fB[CV], bB[CV];
        load_front(fA, tv, 0, lane, nvec);
        load_back (bA, tv, 0, lane, nvec);
        for (int r = 0; r < NR; r += 2) {
            // prefetch round r+1 while testing round r
            if (r + 1 < NR) {
                load_front(fB, tv, r + 1, lane, nvec);
                load_back (bB, tv, r + 1, lane, nvec);
            }
            {
                const unsigned f = orv(fA) | orv(bA);
                if (__ballot_sync(FULL, f != 0u)) {
                    int p = INT_MAX;
                    locate_front(fA, r, lane, p);
                    locate_back (bA, r, lane, nvec, p);
                    pos = __reduce_min_sync(FULL, p);
                    break;
                }
            }
            if (r + 2 < NR) {
                load_front(fA, tv, r + 2, lane, nvec);
                load_back (bA, tv, r + 2, lane, nvec);
            }
            if (r + 1 < NR) {
                const unsigned f = orv(fB) | orv(bB);
                if (__ballot_sync(FULL, f != 0u)) {
                    int p = INT_MAX;
                    locate_front(fB, r + 1, lane, p);
                    locate_back (bB, r + 1, lane, nvec, p);
                    pos = __reduce_min_sync(FULL, p);
                    break;
                }
            }
        }
    }
    // scalar tail (Y % 4 != 0; empty for Y=10000) + defensive fallback
    if (pos < 0) {
        const float* trow = target + (size_t)gw * Y;
        int p = INT_MAX;
        for (int i = (nvec << 2) + lane; i < Y; i += 32)
            if (trow[i] != 0.0f) p = i;
        const int m = __reduce_min_sync(FULL, p);
        pos = (m != INT_MAX) ? m : 0;
    }

    const float sp = __ldg(&irow[pos]);                   // broadcast load

    // --- first accepted among trials 0..15 (scores already in regs) ---
    const bool acc = (lane < BATCH1) && (1.0f + sc_pre - sp >= 0.0f);
    const unsigned m = __ballot_sync(FULL, acc);
    if (m) {
        const int first = __ffs(m) - 1;
        const float sn = __shfl_sync(FULL, sc_pre, first);
        if (lane == 0) {
            const int num_trials = first + 1;
            const float L = logf((float)((Y - 1) / num_trials));
            atomicAdd(out, L * (1.0f - sp + sn));
        }
    } else {
        // --- fallback (rare, ~0.3%): trials BATCH1..T-1, 32 at a time ---
        for (int t0 = BATCH1; t0 < T; t0 += 32) {
            const int t = t0 + lane;
            int c = 0;
            if (t < T) c = __ldg(&neg[(size_t)gw * T + t]);
            const float sc = __ldg(&irow[c]);
            const bool a2 = (t < T) && (1.0f + sc - sp >= 0.0f);
            const unsigned m2 = __ballot_sync(FULL, a2);
            if (m2) {
                const int fl = __ffs(m2) - 1;
                const float sn = __shfl_sync(FULL, sc, fl);
                if (lane == 0) {
                    const int num_trials = t0 + fl + 1;
                    const float L = logf((float)((Y - 1) / num_trials));
                    atomicAdd(out, L * (1.0f - sp + sn));
                }
                break;
            }
        }
    }
}

extern "C" void kernel_launch(void* const* d_in, const int* in_sizes, int n_in,
                              void* d_out, int out_size) {
    const float* input  = (const float*)d_in[0];
    const float* target = (const float*)d_in[1];
    const int*   neg    = (const int*)d_in[2];
    float* out = (float*)d_out;

    const int Y = 10000;                 // fixed by problem spec
    const int B = in_sizes[0] / Y;       // 4096
    const int T = in_sizes[2] / B;       // 128

    cudaMemsetAsync(out, 0, (size_t)out_size * sizeof(float), 0);
    warp_loss_kernel<<<(B + 1) / 2, 64>>>(input, target, neg, out, B, T);
}